// round 8
// baseline (speedup 1.0000x reference)
#include <cuda_runtime.h>
#include <cuda_bf16.h>
#include <math.h>

// HSIC_1855425872455: X [2048,16] fp32 -> scalar fp32
// R8: single persistent kernel, pair-split warp duos.
// Each 32x64 half-tile unit is processed by 4 warps: {w0,w1} cols 0-31,
// {w2,w3} cols 32-63. Both warps of a duo compute identical k[16]; even warp
// accumulates rowA/colA + pairs 0..59, odd warp pairs 60..119.
// Register/thread ~124+ -> launch_bounds(128,3) -> 12 warps/SM.
// Grid 352 (<= 444 co-resident at 3 CTA/SM), 3 units per CTA, t persists.

#define N 2048
#define F 16
#define NPAIR 120
#define TILE 64
#define NT (N / TILE)               // 32
#define NTILES (NT * (NT + 1) / 2)  // 528
#define NUNITS (NTILES * 2)         // 1056 half-tiles
#define GRID 352                    // x3 units each
#define TRI16(a,b) ((a)*15 - (a)*((a)-1)/2 + ((b)-(a)-1))

__device__ float    g_A[N * F];
__device__ float    g_ps[32 * F];
__device__ float    g_pq[32 * F];
__device__ double   g_T[NPAIR];
__device__ unsigned g_sync0, g_sync1;   // monotonic tickets (replay-safe)

__device__ __forceinline__ float ex2f(float x) {
    float r; asm("ex2.approx.f32 %0, %1;" : "=f"(r) : "f"(x)); return r;
}
__device__ __forceinline__ float wred(float v) {
    v += __shfl_xor_sync(0xffffffffu, v, 16);
    v += __shfl_xor_sync(0xffffffffu, v, 8);
    v += __shfl_xor_sync(0xffffffffu, v, 4);
    v += __shfl_xor_sync(0xffffffffu, v, 2);
    v += __shfl_xor_sync(0xffffffffu, v, 1);
    return v;
}
__device__ __forceinline__ void tile_decode(int idx, int& ti, int& tj) {
    int a = 0, rem = idx;
    while (rem >= NT - a) { rem -= NT - a; a++; }
    ti = a; tj = a + rem;
}
__device__ __forceinline__ void gsync(unsigned* ctr) {
    __syncthreads();
    if (threadIdx.x == 0) {
        __threadfence();
        unsigned t = atomicAdd(ctr, 1u);
        unsigned target = (t / GRID + 1u) * GRID;
        while (*(volatile unsigned*)ctr < target) __nanosleep(64);
        __threadfence();
    }
    __syncthreads();
}

// Sweep 32 steps over one 32-col band. EVEN warps also accumulate rowA/colA
// and rotate colA through the lane ring; pair subset [LO,HI) -> t[HI-LO].
template <bool DIAG, bool EVEN, int LO, int HI>
__device__ __forceinline__ void sweep(
    const float* __restrict__ s_xj, const float xi[F],
    float rowA[F], float colA[F], float* __restrict__ t,
    int row_t, int w_j, int l)
{
    #pragma unroll 1
    for (int s = 0; s < 32; s++) {
        const int jl = (w_j << 5) + ((l + s) & 31);
        const float B = DIAG ? ((row_t < jl) ? 0.f : -1024.0f) : 0.f;
        const float* xj = s_xj + jl * 17;
        float k[F];
        #pragma unroll
        for (int c = 0; c < F; c++) {
            float d = xi[c] - xj[c];
            float kk = ex2f(fmaf(d, -d, B));
            k[c] = kk;
            if (EVEN) { rowA[c] += kk; colA[c] += kk; }
        }
        #pragma unroll
        for (int a = 0; a < F; a++)
            #pragma unroll
            for (int b = a + 1; b < F; b++) {
                const int e = TRI16(a, b);
                if (e >= LO && e < HI)
                    t[e - LO] = fmaf(k[a], k[b], t[e - LO]);
            }
        if (EVEN) {
            const int src = (l + 1) & 31;
            #pragma unroll
            for (int c = 0; c < F; c++)
                colA[c] = __shfl_sync(0xffffffffu, colA[c], src);
        }
    }
}

__global__ __launch_bounds__(128, 3) void hsic_all(
    const float* __restrict__ X, float* __restrict__ out)
{
    const int tid = threadIdx.x;
    const int w = tid >> 5, l = tid & 31;
    const int w_j = w >> 1;          // duo: col band
    const bool even = ((w & 1) == 0);
    const int b = blockIdx.x;

    __shared__ float s_sc[F];
    __shared__ float s_xj[TILE * 17];
    __shared__ float s_row[2][32][17];
    __shared__ float s_col[2][32][17];
    __shared__ float s_t[4][60];
    __shared__ float s_ps[128], s_pq[128];
    __shared__ float s_dm[4][NPAIR];
    __shared__ double s_svd[F];
    __shared__ double s_red[128];

    // ---------------- Phase 0: stats partials + zeroing --------------------
    if (b < 32) {
        const int col = tid & 15, part = tid >> 4;
        float s = 0.f, q = 0.f;
        #pragma unroll
        for (int r = part; r < TILE; r += 8) {
            float v = X[(b * TILE + r) * F + col];
            s += v;
            q = fmaf(v, v, q);
        }
        s_ps[tid] = s; s_pq[tid] = q;
        __syncthreads();
        #pragma unroll
        for (int off = 4; off >= 1; off >>= 1) {
            if (part < off) {
                s_ps[tid] += s_ps[tid + off * 16];
                s_pq[tid] += s_pq[tid + off * 16];
            }
            __syncthreads();
        }
        if (tid < F) {
            g_ps[b * F + tid] = s_ps[tid];
            g_pq[b * F + tid] = s_pq[tid];
        }
        float4* A4 = (float4*)g_A;
        A4[b * 256 + tid]       = make_float4(0.f, 0.f, 0.f, 0.f);
        A4[b * 256 + 128 + tid] = make_float4(0.f, 0.f, 0.f, 0.f);
        if (b == 0 && tid < NPAIR) g_T[tid] = 0.0;
    }
    gsync(&g_sync0);

    // ---------------- Phase 1: main ----------------------------------------
    if (tid < F) {
        float s = 0.f, q = 0.f;
        #pragma unroll 4
        for (int bb = 0; bb < 32; bb++) { s += g_ps[bb * F + tid]; q += g_pq[bb * F + tid]; }
        float m1 = s * (1.f / N), m2 = q * (1.f / N);
        float meanD = 2.f * (m2 - m1 * m1);
        s_sc[tid] = sqrtf(1.4426950408889634f / (2.f * meanD));
    }
    __syncthreads();

    float t[60];
    #pragma unroll
    for (int e = 0; e < 60; e++) t[e] = 0.f;

    #pragma unroll 1
    for (int rep = 0; rep < 3; rep++) {
        const int u = b + rep * GRID;   // 0..1055
        int ti, tj;
        tile_decode(u >> 1, ti, tj);
        const int h = u & 1;            // row half of the tile
        const int I0 = ti * TILE + h * 32, J0 = tj * TILE;
        const bool diag = (ti == tj);
        const int row_t = h * 32 + l;   // row index within the 64x64 tile

        // stage 64 J-rows (scaled) into stride-17 smem
        for (int q = tid; q < TILE * F; q += 128) {
            int r = q >> 4, c = q & 15;
            s_xj[r * 17 + c] = X[(J0 + r) * F + c] * s_sc[c];
        }
        float xi[F];
        {
            const float4* p = (const float4*)(X + (I0 + l) * F);
            float4 a = p[0], bv = p[1], c = p[2], d = p[3];
            xi[0]=a.x; xi[1]=a.y; xi[2]=a.z; xi[3]=a.w;
            xi[4]=bv.x; xi[5]=bv.y; xi[6]=bv.z; xi[7]=bv.w;
            xi[8]=c.x; xi[9]=c.y; xi[10]=c.z; xi[11]=c.w;
            xi[12]=d.x; xi[13]=d.y; xi[14]=d.z; xi[15]=d.w;
            #pragma unroll
            for (int cc = 0; cc < F; cc++) xi[cc] *= s_sc[cc];
        }
        float rowA[F], colA[F];
        #pragma unroll
        for (int c = 0; c < F; c++) { rowA[c] = 0.f; colA[c] = 0.f; }
        __syncthreads();

        if (even) {
            if (diag) sweep<true , true , 0, 60 >(s_xj, xi, rowA, colA, t, row_t, w_j, l);
            else      sweep<false, true , 0, 60 >(s_xj, xi, rowA, colA, t, row_t, w_j, l);
        } else {
            if (diag) sweep<true , false, 60, 120>(s_xj, xi, rowA, colA, t, row_t, w_j, l);
            else      sweep<false, false, 60, 120>(s_xj, xi, rowA, colA, t, row_t, w_j, l);
        }
        // even warp of duo w_j: lane l holds colA for col jl = w_j*32 + l

        if (even) {
            #pragma unroll
            for (int c = 0; c < F; c++) {
                s_row[w_j][l][c] = rowA[c];
                s_col[w_j][l][c] = colA[c];
            }
        }
        __syncthreads();
        // rows: 32x16 (sum of the two duos); cols: 64x16 (one duo each)
        for (int idx = tid; idx < 32 * F; idx += 128) {
            const int ii = idx >> 4, c = idx & 15;
            atomicAdd(&g_A[(I0 + ii) * F + c],
                      s_row[0][ii][c] + s_row[1][ii][c]);
        }
        for (int idx = tid; idx < TILE * F; idx += 128) {
            const int jj = idx >> 4, c = idx & 15;
            atomicAdd(&g_A[(J0 + jj) * F + c], s_col[jj >> 5][jj & 31][c]);
        }
        __syncthreads();
    }

    // t epilogue (once per CTA)
    #pragma unroll
    for (int e = 0; e < 60; e++) t[e] = wred(t[e]);
    if (l == 0) {
        #pragma unroll
        for (int e = 0; e < 60; e++) s_t[w][e] = t[e];
    }
    __syncthreads();
    for (int e = tid; e < NPAIR; e += 128) {
        float v = (e < 60) ? (s_t[0][e] + s_t[2][e])
                           : (s_t[1][e - 60] + s_t[3][e - 60]);
        atomicAdd(&g_T[e], (double)v);
    }
    gsync(&g_sync1);

    // ---------------- Phase 2: finish (CTA 0 only) --------------------------
    if (b != 0) return;
    {
        float acc[NPAIR], sv[F];
        #pragma unroll
        for (int e = 0; e < NPAIR; e++) acc[e] = 0.f;
        #pragma unroll
        for (int c = 0; c < F; c++) sv[c] = 0.f;

        #pragma unroll 1
        for (int it = 0; it < 16; it++) {
            const int r = w * 512 + it * 32 + l;
            const float4* p = (const float4*)(g_A + r * F);
            float4 a = p[0], bv = p[1], c = p[2], d = p[3];
            float rv[F] = {a.x,a.y,a.z,a.w, bv.x,bv.y,bv.z,bv.w,
                           c.x,c.y,c.z,c.w, d.x,d.y,d.z,d.w};
            #pragma unroll
            for (int aa = 0; aa < F; aa++) {
                sv[aa] += rv[aa];
                #pragma unroll
                for (int bb = aa + 1; bb < F; bb++)
                    acc[TRI16(aa, bb)] = fmaf(rv[aa], rv[bb], acc[TRI16(aa, bb)]);
            }
        }
        #pragma unroll
        for (int e = 0; e < NPAIR; e++) acc[e] = wred(acc[e]);
        #pragma unroll
        for (int c = 0; c < F; c++) sv[c] = wred(sv[c]);
        if (l == 0) {
            #pragma unroll
            for (int e = 0; e < NPAIR; e++) s_dm[w][e] = acc[e];
            #pragma unroll
            for (int c = 0; c < F; c++) s_row[0][w][c] = sv[c];
        }
        __syncthreads();
        if (tid < F) {
            double s = 0.0;
            #pragma unroll
            for (int ww = 0; ww < 4; ww++) s += (double)s_row[0][ww][tid];
            s_svd[tid] = s;
        }
        __syncthreads();

        double v = 0.0;
        if (tid < NPAIR) {
            int a = 0, rem = tid;
            while (rem >= 15 - a) { rem -= 15 - a; a++; }
            int bb2 = a + 1 + rem;
            double dm = (double)s_dm[0][tid] + (double)s_dm[1][tid]
                      + (double)s_dm[2][tid] + (double)s_dm[3][tid];
            const double n = (double)N;
            double T = 2.0 * g_T[tid];              // strict-upper weight
            double c0 = 1.0 / (n * (n - 3.0));
            double h = c0 * (T + s_svd[a] * s_svd[bb2] / ((n - 1.0) * (n - 2.0))
                               - (2.0 / (n - 2.0)) * dm);
            v = h * h;
        }
        s_red[tid] = v;
        __syncthreads();
        #pragma unroll
        for (int off = 64; off >= 1; off >>= 1) {
            if (tid < off) s_red[tid] += s_red[tid + off];
            __syncthreads();
        }
        if (tid == 0) out[0] = (float)s_red[0];
    }
}

extern "C" void kernel_launch(void* const* d_in, const int* in_sizes, int n_in,
                              void* d_out, int out_size) {
    const float* X = (const float*)d_in[0];
    hsic_all<<<GRID, 128>>>(X, (float*)d_out);
}

// round 10
// speedup vs baseline: 1.4120x; 1.4120x over previous
#include <cuda_runtime.h>
#include <cuda_bf16.h>
#include <math.h>

// HSIC_1855425872455: X [2048,16] fp32 -> scalar fp32
// R10 (= R9 resubmit after infra failure): R6 3-kernel structure + chain-free
// systolic: colA is lane-fixed and the per-step k vector is shuffled to its
// column owner (no loop-carried SHFL dependency). Everything else identical
// to the 49.9us R6 baseline.

#define N 2048
#define F 16
#define NPAIR 120
#define TILE 64
#define NT (N / TILE)              // 32
#define NBLK (NT * (NT + 1) / 2)   // 528
#define GRID_MAIN 264              // x2 tiles each
#define TRI16(a,b) ((a)*15 - (a)*((a)-1)/2 + ((b)-(a)-1))

__device__ float  g_A[N * F];
__device__ float  g_ps[32 * F];    // per-block column sums
__device__ float  g_pq[32 * F];    // per-block column sums of squares
__device__ double g_T[NPAIR];

__device__ __forceinline__ float ex2f(float x) {
    float r; asm("ex2.approx.f32 %0, %1;" : "=f"(r) : "f"(x)); return r;
}
__device__ __forceinline__ float wred(float v) {
    v += __shfl_xor_sync(0xffffffffu, v, 16);
    v += __shfl_xor_sync(0xffffffffu, v, 8);
    v += __shfl_xor_sync(0xffffffffu, v, 4);
    v += __shfl_xor_sync(0xffffffffu, v, 2);
    v += __shfl_xor_sync(0xffffffffu, v, 1);
    return v;
}
__device__ __forceinline__ void tile_decode(int idx, int& ti, int& tj) {
    int a = 0, rem = idx;
    while (rem >= NT - a) { rem -= NT - a; a++; }
    ti = a; tj = a + rem;
}

// ---------------------------------------------------------------------------
// k1: grid 32 x 256. Block b: column partial sums for rows [64b, 64b+64),
// zero its slice of g_A; block 0 zeroes g_T.
// ---------------------------------------------------------------------------
__global__ void hsic_stats(const float* __restrict__ X) {
    const int b = blockIdx.x, tid = threadIdx.x;
    const int col = tid & 15, part = tid >> 4;
    __shared__ float shs[256], shq[256];
    float s = 0.f, q = 0.f;
    for (int r = part; r < TILE; r += 16) {
        float v = X[(b * TILE + r) * F + col];
        s += v;
        q = fmaf(v, v, q);
    }
    shs[tid] = s; shq[tid] = q;
    __syncthreads();
    #pragma unroll
    for (int off = 8; off >= 1; off >>= 1) {
        if (part < off) {
            shs[tid] += shs[tid + off * 16];
            shq[tid] += shq[tid + off * 16];
        }
        __syncthreads();
    }
    if (tid < F) {
        g_ps[b * F + tid] = shs[tid];
        g_pq[b * F + tid] = shq[tid];
    }
    float4* A4 = (float4*)g_A;
    if (tid < 256) A4[b * 256 + tid] = make_float4(0.f, 0.f, 0.f, 0.f);
    if (b == 0 && tid < NPAIR) g_T[tid] = 0.0;
}

// ---------------------------------------------------------------------------
// k2 inner: 32-step sweep over one 64x64 tile half-pair.
// Chain-free systolic: lane l computes k for column jl=(l+s)&31 (within its
// band), accumulates rowA locally, and each lane (as column owner) pulls the
// k destined for its fixed column via shfl from lane (l-s)&31.
// DIAG=true applies strict-upper mask in the ex2 arg (masked k == 0 exactly).
// ---------------------------------------------------------------------------
template <bool DIAG>
__device__ __forceinline__ void tile_sweep(
    const float* __restrict__ s_xj, const float xi[F],
    float rowA[F], float colA[F], float t[NPAIR],
    int il, int w_j, int l)
{
    #pragma unroll 2
    for (int s = 0; s < 32; s++) {
        const int jl = (w_j << 5) + ((l + s) & 31);
        const float B = DIAG ? ((il < jl) ? 0.f : -1024.0f) : 0.f;
        const float* xj = s_xj + jl * 17;
        float k[F];
        #pragma unroll
        for (int c = 0; c < F; c++) {
            float d = xi[c] - xj[c];
            float kk = ex2f(fmaf(d, -d, B));
            k[c] = kk;
            rowA[c] += kk;
        }
        #pragma unroll
        for (int a = 0; a < F; a++)
            #pragma unroll
            for (int b = a + 1; b < F; b++)
                t[TRI16(a, b)] = fmaf(k[a], k[b], t[TRI16(a, b)]);
        // column owner (lane l owns column band+l) pulls k from producer lane
        const int src = (l - s) & 31;
        #pragma unroll
        for (int c = 0; c < F; c++)
            colA[c] += __shfl_sync(0xffffffffu, k[c], src);
    }
}

// ---------------------------------------------------------------------------
// k2: main. 264 blocks x 128 threads (2 CTAs/SM), 2 tiles each.
// Reads raw X; scale applied during staging. Stride-17 smem (conflict-free).
// Strict i<j counting: T weight 2 downstream, A needs no self-correction.
// ---------------------------------------------------------------------------
__global__ __launch_bounds__(128, 2) void hsic_main(const float* __restrict__ X) {
    const int tid = threadIdx.x;
    const int w = tid >> 5, l = tid & 31;
    const int w_i = w >> 1, w_j = w & 1;
    __shared__ float s_sc[F];
    __shared__ float s_xj[TILE * 17];
    __shared__ float s_row[4][32][17];
    __shared__ float s_col[4][32][17];
    __shared__ float s_t[4][NPAIR];

    if (tid < F) {
        float s = 0.f, q = 0.f;
        #pragma unroll 4
        for (int b = 0; b < 32; b++) { s += g_ps[b * F + tid]; q += g_pq[b * F + tid]; }
        float m1 = s * (1.f / N), m2 = q * (1.f / N);
        float meanD = 2.f * (m2 - m1 * m1);
        s_sc[tid] = sqrtf(1.4426950408889634f / (2.f * meanD));
    }
    __syncthreads();

    float t[NPAIR];
    #pragma unroll
    for (int e = 0; e < NPAIR; e++) t[e] = 0.f;

    #pragma unroll 1
    for (int rep = 0; rep < 2; rep++) {
        int ti, tj;
        tile_decode(blockIdx.x + rep * GRID_MAIN, ti, tj);
        const int I0 = ti * TILE, J0 = tj * TILE;
        const bool diag = (ti == tj);

        for (int q = tid; q < TILE * F; q += 128) {
            int r = q >> 4, c = q & 15;
            s_xj[r * 17 + c] = X[(J0 + r) * F + c] * s_sc[c];
        }
        const int il = (w_i << 5) + l;
        const int iiG = I0 + il;
        float xi[F];
        {
            const float4* p = (const float4*)(X + iiG * F);
            float4 a = p[0], b = p[1], c = p[2], d = p[3];
            xi[0]=a.x; xi[1]=a.y; xi[2]=a.z; xi[3]=a.w;
            xi[4]=b.x; xi[5]=b.y; xi[6]=b.z; xi[7]=b.w;
            xi[8]=c.x; xi[9]=c.y; xi[10]=c.z; xi[11]=c.w;
            xi[12]=d.x; xi[13]=d.y; xi[14]=d.z; xi[15]=d.w;
            #pragma unroll
            for (int cc = 0; cc < F; cc++) xi[cc] *= s_sc[cc];
        }
        float rowA[F], colA[F];
        #pragma unroll
        for (int c = 0; c < F; c++) { rowA[c] = 0.f; colA[c] = 0.f; }
        __syncthreads();

        if (diag) tile_sweep<true >(s_xj, xi, rowA, colA, t, il, w_j, l);
        else      tile_sweep<false>(s_xj, xi, rowA, colA, t, il, w_j, l);
        // lane l holds colA for column jl = w_j*32 + l (lane-fixed owner)

        #pragma unroll
        for (int c = 0; c < F; c++) {
            s_row[w][l][c] = rowA[c];
            s_col[w][l][c] = colA[c];
        }
        __syncthreads();
        for (int idx = tid; idx < TILE * F; idx += 128) {
            const int ii = idx >> 4, c = idx & 15;
            const int ib = ii >> 5, ir = ii & 31;
            float rv = s_row[ib * 2][ir][c] + s_row[ib * 2 + 1][ir][c];
            atomicAdd(&g_A[(I0 + ii) * F + c], rv);
            float cv = s_col[ib][ir][c] + s_col[ib + 2][ir][c];
            atomicAdd(&g_A[(J0 + ii) * F + c], cv);
        }
        __syncthreads();
    }

    #pragma unroll
    for (int e = 0; e < NPAIR; e++) t[e] = wred(t[e]);
    if (l == 0) {
        #pragma unroll
        for (int e = 0; e < NPAIR; e++) s_t[w][e] = t[e];
    }
    __syncthreads();
    for (int e = tid; e < NPAIR; e += 128)
        atomicAdd(&g_T[e],
                  (double)(s_t[0][e] + s_t[1][e] + s_t[2][e] + s_t[3][e]));
}

// ---------------------------------------------------------------------------
// k3: finish. 1 block x 256 threads (8 warps). Warp w owns ALL 120 pairs over
// rows [256w, 256w+256): register accumulators, coalesced LDG, one wred pass.
// Then fp64 combine of h over strict upper triangle; fp32 scalar out.
// ---------------------------------------------------------------------------
__global__ __launch_bounds__(256, 1) void hsic_finish(float* __restrict__ out) {
    const int tid = threadIdx.x;
    const int w = tid >> 5, l = tid & 31;
    __shared__ float  s_dm8[8][NPAIR];
    __shared__ float  s_sv8[8][F];
    __shared__ double s_svd[F];
    __shared__ double s_red[128];

    float acc[NPAIR], sv[F];
    #pragma unroll
    for (int e = 0; e < NPAIR; e++) acc[e] = 0.f;
    #pragma unroll
    for (int c = 0; c < F; c++) sv[c] = 0.f;

    #pragma unroll 1
    for (int it = 0; it < 8; it++) {
        const int r = w * 256 + it * 32 + l;
        const float4* p = (const float4*)(g_A + r * F);
        float4 a = p[0], b = p[1], c = p[2], d = p[3];
        float rv[F] = {a.x,a.y,a.z,a.w, b.x,b.y,b.z,b.w,
                       c.x,c.y,c.z,c.w, d.x,d.y,d.z,d.w};
        #pragma unroll
        for (int aa = 0; aa < F; aa++) {
            sv[aa] += rv[aa];
            #pragma unroll
            for (int bb = aa + 1; bb < F; bb++)
                acc[TRI16(aa, bb)] = fmaf(rv[aa], rv[bb], acc[TRI16(aa, bb)]);
        }
    }
    #pragma unroll
    for (int e = 0; e < NPAIR; e++) acc[e] = wred(acc[e]);
    #pragma unroll
    for (int c = 0; c < F; c++) sv[c] = wred(sv[c]);
    if (l == 0) {
        #pragma unroll
        for (int e = 0; e < NPAIR; e++) s_dm8[w][e] = acc[e];
        #pragma unroll
        for (int c = 0; c < F; c++) s_sv8[w][c] = sv[c];
    }
    __syncthreads();
    if (tid < F) {
        double s = 0.0;
        #pragma unroll
        for (int ww = 0; ww < 8; ww++) s += (double)s_sv8[ww][tid];
        s_svd[tid] = s;
    }
    __syncthreads();

    double v = 0.0;
    if (tid < NPAIR) {
        int a = 0, rem = tid;
        while (rem >= 15 - a) { rem -= 15 - a; a++; }
        int b = a + 1 + rem;
        double dm = 0.0;
        #pragma unroll
        for (int ww = 0; ww < 8; ww++) dm += (double)s_dm8[ww][tid];
        const double n = (double)N;
        double T = 2.0 * g_T[tid];                 // strict-upper weight
        double c0 = 1.0 / (n * (n - 3.0));
        double h = c0 * (T + s_svd[a] * s_svd[b] / ((n - 1.0) * (n - 2.0))
                           - (2.0 / (n - 2.0)) * dm);
        v = h * h;
    }
    if (tid < 128) s_red[tid] = v;
    __syncthreads();
    #pragma unroll
    for (int off = 64; off >= 1; off >>= 1) {
        if (tid < off) s_red[tid] += s_red[tid + off];
        __syncthreads();
    }
    if (tid == 0) out[0] = (float)s_red[0];
}

extern "C" void kernel_launch(void* const* d_in, const int* in_sizes, int n_in,
                              void* d_out, int out_size) {
    const float* X = (const float*)d_in[0];
    hsic_stats<<<32, 256>>>(X);
    hsic_main<<<GRID_MAIN, 128>>>(X);
    hsic_finish<<<1, 256>>>((float*)d_out);
}

// round 12
// speedup vs baseline: 1.4391x; 1.0192x over previous
#include <cuda_runtime.h>
#include <cuda_bf16.h>
#include <math.h>

// HSIC_1855425872455: X [2048,16] fp32 -> scalar fp32
// R12 = R11 with the phase-2 S-column coverage fix (strided NPAIR+F scatter).
//   Phase 0: CTAs 0-31 column-stat partials + zero g_A/g_T/g_Dm/g_S. gsync.
//   Phase 1: symmetric tiled main (chain-free systolic, stride-17 smem,
//            DIAG-masked, t persists over 2 tiles). gsync.
//   Phase 2: CTAs 0-31 compute Dm/S partials (64 rows each) -> fp64 atomics.
//            gsync.
//   Phase 3: CTA 0 combines 120 h values -> out.
// launch_bounds(128,2): 2 CTA/SM -> 296 slots >= 264 CTAs co-resident ->
// ticket gsync deadlock-free; monotonic counters replay-safe.

#define N 2048
#define F 16
#define NPAIR 120
#define TILE 64
#define NT (N / TILE)              // 32
#define NBLK (NT * (NT + 1) / 2)   // 528
#define GRID 264                   // x2 tiles each
#define TRI16(a,b) ((a)*15 - (a)*((a)-1)/2 + ((b)-(a)-1))

__device__ float    g_A[N * F];
__device__ float    g_ps[32 * F];
__device__ float    g_pq[32 * F];
__device__ double   g_T[NPAIR];
__device__ double   g_Dm[NPAIR];
__device__ double   g_S[F];
__device__ unsigned g_sync0, g_sync1, g_sync2;   // monotonic tickets

__device__ __forceinline__ float ex2f(float x) {
    float r; asm("ex2.approx.f32 %0, %1;" : "=f"(r) : "f"(x)); return r;
}
__device__ __forceinline__ float wred(float v) {
    v += __shfl_xor_sync(0xffffffffu, v, 16);
    v += __shfl_xor_sync(0xffffffffu, v, 8);
    v += __shfl_xor_sync(0xffffffffu, v, 4);
    v += __shfl_xor_sync(0xffffffffu, v, 2);
    v += __shfl_xor_sync(0xffffffffu, v, 1);
    return v;
}
__device__ __forceinline__ void tile_decode(int idx, int& ti, int& tj) {
    int a = 0, rem = idx;
    while (rem >= NT - a) { rem -= NT - a; a++; }
    ti = a; tj = a + rem;
}
__device__ __forceinline__ void gsync(unsigned* ctr) {
    __syncthreads();
    if (threadIdx.x == 0) {
        __threadfence();
        unsigned t = atomicAdd(ctr, 1u);
        unsigned target = (t / GRID + 1u) * GRID;
        while (*(volatile unsigned*)ctr < target) __nanosleep(64);
        __threadfence();
    }
    __syncthreads();
}

// Chain-free systolic sweep: lane l computes k for column jl=(l+s)&31 in its
// band, accumulates rowA locally; lane-fixed colA owner pulls k via shfl.
template <bool DIAG>
__device__ __forceinline__ void tile_sweep(
    const float* __restrict__ s_xj, const float xi[F],
    float rowA[F], float colA[F], float t[NPAIR],
    int il, int w_j, int l)
{
    #pragma unroll 2
    for (int s = 0; s < 32; s++) {
        const int jl = (w_j << 5) + ((l + s) & 31);
        const float B = DIAG ? ((il < jl) ? 0.f : -1024.0f) : 0.f;
        const float* xj = s_xj + jl * 17;
        float k[F];
        #pragma unroll
        for (int c = 0; c < F; c++) {
            float d = xi[c] - xj[c];
            float kk = ex2f(fmaf(d, -d, B));
            k[c] = kk;
            rowA[c] += kk;
        }
        #pragma unroll
        for (int a = 0; a < F; a++)
            #pragma unroll
            for (int b = a + 1; b < F; b++)
                t[TRI16(a, b)] = fmaf(k[a], k[b], t[TRI16(a, b)]);
        const int src = (l - s) & 31;
        #pragma unroll
        for (int c = 0; c < F; c++)
            colA[c] += __shfl_sync(0xffffffffu, k[c], src);
    }
}

__global__ __launch_bounds__(128, 2) void hsic_all(
    const float* __restrict__ X, float* __restrict__ out)
{
    const int tid = threadIdx.x;
    const int w = tid >> 5, l = tid & 31;
    const int w_i = w >> 1, w_j = w & 1;
    const int b = blockIdx.x;

    __shared__ float s_sc[F];
    __shared__ float s_xj[TILE * 17];
    __shared__ float s_row[4][32][17];
    __shared__ float s_col[4][32][17];
    __shared__ float s_t[4][NPAIR];
    __shared__ float s_ps[128], s_pq[128];
    __shared__ float s_sv4[4][F];
    __shared__ double s_red[128];

    // ---------------- Phase 0: stats partials + zeroing --------------------
    if (b < 32) {
        const int col = tid & 15, part = tid >> 4;   // 8 partials per column
        float s = 0.f, q = 0.f;
        #pragma unroll
        for (int r = part; r < TILE; r += 8) {
            float v = X[(b * TILE + r) * F + col];
            s += v;
            q = fmaf(v, v, q);
        }
        s_ps[tid] = s; s_pq[tid] = q;
        __syncthreads();
        #pragma unroll
        for (int off = 4; off >= 1; off >>= 1) {
            if (part < off) {
                s_ps[tid] += s_ps[tid + off * 16];
                s_pq[tid] += s_pq[tid + off * 16];
            }
            __syncthreads();
        }
        if (tid < F) {
            g_ps[b * F + tid] = s_ps[tid];
            g_pq[b * F + tid] = s_pq[tid];
        }
        float4* A4 = (float4*)g_A;
        A4[b * 256 + tid]       = make_float4(0.f, 0.f, 0.f, 0.f);
        A4[b * 256 + 128 + tid] = make_float4(0.f, 0.f, 0.f, 0.f);
        if (b == 0) {
            if (tid < NPAIR) { g_T[tid] = 0.0; g_Dm[tid] = 0.0; }
            if (tid < F) g_S[tid] = 0.0;
        }
    }
    gsync(&g_sync0);

    // ---------------- Phase 1: main ----------------------------------------
    if (tid < F) {
        float s = 0.f, q = 0.f;
        #pragma unroll 4
        for (int bb = 0; bb < 32; bb++) { s += g_ps[bb * F + tid]; q += g_pq[bb * F + tid]; }
        float m1 = s * (1.f / N), m2 = q * (1.f / N);
        float meanD = 2.f * (m2 - m1 * m1);
        s_sc[tid] = sqrtf(1.4426950408889634f / (2.f * meanD));
    }
    __syncthreads();

    {
        float t[NPAIR];
        #pragma unroll
        for (int e = 0; e < NPAIR; e++) t[e] = 0.f;

        #pragma unroll 1
        for (int rep = 0; rep < 2; rep++) {
            int ti, tj;
            tile_decode(b + rep * GRID, ti, tj);
            const int I0 = ti * TILE, J0 = tj * TILE;
            const bool diag = (ti == tj);

            for (int q = tid; q < TILE * F; q += 128) {
                int r = q >> 4, c = q & 15;
                s_xj[r * 17 + c] = X[(J0 + r) * F + c] * s_sc[c];
            }
            const int il = (w_i << 5) + l;
            float xi[F];
            {
                const float4* p = (const float4*)(X + (I0 + il) * F);
                float4 a = p[0], bv = p[1], c = p[2], d = p[3];
                xi[0]=a.x; xi[1]=a.y; xi[2]=a.z; xi[3]=a.w;
                xi[4]=bv.x; xi[5]=bv.y; xi[6]=bv.z; xi[7]=bv.w;
                xi[8]=c.x; xi[9]=c.y; xi[10]=c.z; xi[11]=c.w;
                xi[12]=d.x; xi[13]=d.y; xi[14]=d.z; xi[15]=d.w;
                #pragma unroll
                for (int cc = 0; cc < F; cc++) xi[cc] *= s_sc[cc];
            }
            float rowA[F], colA[F];
            #pragma unroll
            for (int c = 0; c < F; c++) { rowA[c] = 0.f; colA[c] = 0.f; }
            __syncthreads();

            if (diag) tile_sweep<true >(s_xj, xi, rowA, colA, t, il, w_j, l);
            else      tile_sweep<false>(s_xj, xi, rowA, colA, t, il, w_j, l);
            // lane l holds colA for column jl = w_j*32 + l

            #pragma unroll
            for (int c = 0; c < F; c++) {
                s_row[w][l][c] = rowA[c];
                s_col[w][l][c] = colA[c];
            }
            __syncthreads();
            for (int idx = tid; idx < TILE * F; idx += 128) {
                const int ii = idx >> 4, c = idx & 15;
                const int ib = ii >> 5, ir = ii & 31;
                float rv = s_row[ib * 2][ir][c] + s_row[ib * 2 + 1][ir][c];
                atomicAdd(&g_A[(I0 + ii) * F + c], rv);
                float cv = s_col[ib][ir][c] + s_col[ib + 2][ir][c];
                atomicAdd(&g_A[(J0 + ii) * F + c], cv);
            }
            __syncthreads();
        }

        #pragma unroll
        for (int e = 0; e < NPAIR; e++) t[e] = wred(t[e]);
        if (l == 0) {
            #pragma unroll
            for (int e = 0; e < NPAIR; e++) s_t[w][e] = t[e];
        }
        __syncthreads();
        for (int e = tid; e < NPAIR; e += 128)
            atomicAdd(&g_T[e],
                      (double)(s_t[0][e] + s_t[1][e] + s_t[2][e] + s_t[3][e]));
    }
    gsync(&g_sync1);

    // ---------------- Phase 2: distributed Dm/S (CTAs 0-31) -----------------
    if (b < 32) {
        // warp w: rows [64b + 16w, +16); lanes 16..31 contribute zeros
        float acc[NPAIR], sv[F];
        #pragma unroll
        for (int e = 0; e < NPAIR; e++) acc[e] = 0.f;
        #pragma unroll
        for (int c = 0; c < F; c++) sv[c] = 0.f;
        if (l < 16) {
            const int r = b * TILE + w * 16 + l;
            const float4* p = (const float4*)(g_A + r * F);
            float4 a = p[0], bv = p[1], c = p[2], d = p[3];
            float rv[F] = {a.x,a.y,a.z,a.w, bv.x,bv.y,bv.z,bv.w,
                           c.x,c.y,c.z,c.w, d.x,d.y,d.z,d.w};
            #pragma unroll
            for (int aa = 0; aa < F; aa++) {
                sv[aa] = rv[aa];
                #pragma unroll
                for (int bb = aa + 1; bb < F; bb++)
                    acc[TRI16(aa, bb)] = rv[aa] * rv[bb];
            }
        }
        #pragma unroll
        for (int e = 0; e < NPAIR; e++) acc[e] = wred(acc[e]);
        #pragma unroll
        for (int c = 0; c < F; c++) sv[c] = wred(sv[c]);
        if (l == 0) {
            #pragma unroll
            for (int e = 0; e < NPAIR; e++) s_t[w][e] = acc[e];
            #pragma unroll
            for (int c = 0; c < F; c++) s_sv4[w][c] = sv[c];
        }
        __syncthreads();
        // FIX (R11 bug): strided scatter covers all NPAIR + F slots with 128
        // threads; the old if/else guard reached only S columns 0..7.
        for (int e2 = tid; e2 < NPAIR + F; e2 += 128) {
            if (e2 < NPAIR) {
                atomicAdd(&g_Dm[e2],
                          (double)(s_t[0][e2] + s_t[1][e2] + s_t[2][e2] + s_t[3][e2]));
            } else {
                const int c = e2 - NPAIR;
                atomicAdd(&g_S[c],
                          (double)(s_sv4[0][c] + s_sv4[1][c] + s_sv4[2][c] + s_sv4[3][c]));
            }
        }
    }
    gsync(&g_sync2);

    // ---------------- Phase 3: combine (CTA 0) -------------------------------
    if (b != 0) return;
    {
        double v = 0.0;
        if (tid < NPAIR) {
            int a = 0, rem = tid;
            while (rem >= 15 - a) { rem -= 15 - a; a++; }
            int bb2 = a + 1 + rem;
            const double n = (double)N;
            double T = 2.0 * g_T[tid];              // strict-upper weight
            double c0 = 1.0 / (n * (n - 3.0));
            double h = c0 * (T + g_S[a] * g_S[bb2] / ((n - 1.0) * (n - 2.0))
                               - (2.0 / (n - 2.0)) * g_Dm[tid]);
            v = h * h;
        }
        s_red[tid] = v;
        __syncthreads();
        #pragma unroll
        for (int off = 64; off >= 1; off >>= 1) {
            if (tid < off) s_red[tid] += s_red[tid + off];
            __syncthreads();
        }
        if (tid == 0) out[0] = (float)s_red[0];
    }
}

extern "C" void kernel_launch(void* const* d_in, const int* in_sizes, int n_in,
                              void* d_out, int out_size) {
    const float* X = (const float*)d_in[0];
    hsic_all<<<GRID, 128>>>(X, (float*)d_out);
}